// round 11
// baseline (speedup 1.0000x reference)
#include <cuda_runtime.h>
#include <cuda_fp16.h>
#include <cstdint>

#define B_SZ  2
#define N_TOK 512
#define D     64
#define H     128
#define OUTD  64
#define NTILES 4096
#define PAIR_GRID 296

// ---------------------------------------------------------------------------
// Scratch (device globals)
// ---------------------------------------------------------------------------
__device__ float    g_xa[B_SZ * N_TOK * H];        // x @ W1[:D] + b1  (fp32)
__device__ float    g_xb[B_SZ * N_TOK * H];        // x @ W1[D:]       (fp32)
__device__ uint32_t g_W2t[H * H / 2];              // W2^T fp16, [n][k] (half2 words)
__device__ float    g_pooled_part[B_SZ * 32 * H];  // 32 contention slots per batch
__device__ float    g_Mpart[4 * H * H];            // k-sliced partials of W3 @ V1
__device__ float    g_d[H];                        // N^2*(b3@V1) + c1
__device__ int      g_ticket;                      // pair-kernel work queue
__device__ float    g_dummy;                       // keep warm-loads alive

__device__ __forceinline__ uint32_t smem_u32(const void* p) {
    uint32_t a;
    asm("{ .reg .u64 tmp; cvta.to.shared.u64 tmp, %1; cvt.u32.u64 %0, tmp; }"
        : "=r"(a) : "l"(p));
    return a;
}
__device__ __forceinline__ void ldmatrix_x4(uint32_t* r, uint32_t addr) {
    asm volatile("ldmatrix.sync.aligned.m8n8.x4.shared.b16 {%0,%1,%2,%3}, [%4];"
        : "=r"(r[0]), "=r"(r[1]), "=r"(r[2]), "=r"(r[3]) : "r"(addr));
}
__device__ __forceinline__ void mma_f16(float* c, const uint32_t* a,
                                        uint32_t b0, uint32_t b1) {
    asm volatile(
        "mma.sync.aligned.m16n8k16.row.col.f32.f16.f16.f32 "
        "{%0,%1,%2,%3}, {%4,%5,%6,%7}, {%8,%9}, {%0,%1,%2,%3};"
        : "+f"(c[0]), "+f"(c[1]), "+f"(c[2]), "+f"(c[3])
        : "r"(a[0]), "r"(a[1]), "r"(a[2]), "r"(a[3]), "r"(b0), "r"(b1));
}

// SMEM layout (bytes). Row stride for A/B tiles: 272B (256B data + 16B pad)
#define RSTRIDE  272u
#define OFF_A    0u
#define OFF_B    34816u     // 128*272
#define OFF_XA   69632u     // 8  rows x 128 f32
#define OFF_XB   73728u     // 16 rows x 128 f32
#define OFF_B2   81920u     // 128 f32
#define OFF_RED  82432u     // 8 x 32 f32
#define SMEM_BYTES 83456u

// ---------------------------------------------------------------------------
// Merged setup kernel. Block roles (longest chains first):
//   [0,512)    MCOMP: g_Mpart[s][k][h] = sum_{m in slice s} W3[k][m]*V1[m][h]
//   512        DVEC : g_d[h] = N^2*(b3@V1)[h] + c1[h]; reset ticket
//   [513,641)  CONV : W2 -> W2^T fp16; zero pooled slots
//   [641,649)  WARM : touch V2 into L2
//   [649,1161) PREP : xa/xb = x @ W1 halves (b1 folded into xa)
// ---------------------------------------------------------------------------
__global__ __launch_bounds__(128) void setup_kernel(const float* __restrict__ x,
                                                    const float* __restrict__ W1,
                                                    const float* __restrict__ b1,
                                                    const float* __restrict__ W2,
                                                    const float* __restrict__ W3,
                                                    const float* __restrict__ b3,
                                                    const float* __restrict__ V1,
                                                    const float* __restrict__ c1,
                                                    const float* __restrict__ V2)
{
    __shared__ float sbuf[128];
    const int blk = blockIdx.x;
    const int t = threadIdx.x;

    if (blk < 512) {                       // ---- MCOMP (4-way k-split) ----
        const int k = blk >> 2, s = blk & 3;
        const int m0 = s * 32;
        if (t < 32) sbuf[t] = W3[k * H + m0 + t];
        __syncthreads();
        float a0 = 0.f, a1 = 0.f, a2 = 0.f, a3 = 0.f;
        float a4 = 0.f, a5 = 0.f, a6 = 0.f, a7 = 0.f;
#pragma unroll
        for (int m = 0; m < 32; m += 8) {
            a0 = fmaf(sbuf[m    ], V1[(m0 + m    ) * H + t], a0);
            a1 = fmaf(sbuf[m + 1], V1[(m0 + m + 1) * H + t], a1);
            a2 = fmaf(sbuf[m + 2], V1[(m0 + m + 2) * H + t], a2);
            a3 = fmaf(sbuf[m + 3], V1[(m0 + m + 3) * H + t], a3);
            a4 = fmaf(sbuf[m + 4], V1[(m0 + m + 4) * H + t], a4);
            a5 = fmaf(sbuf[m + 5], V1[(m0 + m + 5) * H + t], a5);
            a6 = fmaf(sbuf[m + 6], V1[(m0 + m + 6) * H + t], a6);
            a7 = fmaf(sbuf[m + 7], V1[(m0 + m + 7) * H + t], a7);
        }
        g_Mpart[s * (H * H) + k * H + t] =
            ((a0 + a1) + (a2 + a3)) + ((a4 + a5) + (a6 + a7));
    } else if (blk == 512) {               // ---- DVEC ----
        sbuf[t] = b3[t];
        __syncthreads();
        float a0 = 0.f, a1 = 0.f, a2 = 0.f, a3 = 0.f;
#pragma unroll 8
        for (int m = 0; m < H; m += 4) {
            a0 = fmaf(sbuf[m    ], V1[(m    ) * H + t], a0);
            a1 = fmaf(sbuf[m + 1], V1[(m + 1) * H + t], a1);
            a2 = fmaf(sbuf[m + 2], V1[(m + 2) * H + t], a2);
            a3 = fmaf(sbuf[m + 3], V1[(m + 3) * H + t], a3);
        }
        g_d[t] = 262144.0f * ((a0 + a1) + (a2 + a3)) + c1[t];
        if (t == 0) g_ticket = 0;
    } else if (blk < 641) {                // ---- CONV ----
        const int n = blk - 513;
        if (t < 64) {
            const int kk = t;
            __half2 v = __floats2half2_rn(W2[(2 * kk) * H + n],
                                          W2[(2 * kk + 1) * H + n]);
            g_W2t[n * 64 + kk] = *(uint32_t*)&v;
        } else {
            g_pooled_part[n * 64 + (t - 64)] = 0.f;   // 128*64 = 8192 slots
        }
    } else if (blk < 649) {                // ---- WARM V2 ----
        const int e = (blk - 641) * 1024 + t * 8;
        float s = 0.f;
#pragma unroll
        for (int i = 0; i < 8; ++i) s += V2[e + i];
        if (s == 1.2345e30f) g_dummy = s;
    } else {                               // ---- PREP ----
        const int row0 = (blk - 649) * 2;
        if (t < 2 * D) sbuf[t] = x[row0 * D + t];
        __syncthreads();
        const int h = t;
        float a0 = 0.f, a1 = 0.f, b0 = 0.f, b1v = 0.f;
#pragma unroll 16
        for (int d = 0; d < D; ++d) {
            const float wa = W1[d * H + h];
            const float wb = W1[(D + d) * H + h];
            a0  = fmaf(sbuf[d],      wa, a0);
            a1  = fmaf(sbuf[64 + d], wa, a1);
            b0  = fmaf(sbuf[d],      wb, b0);
            b1v = fmaf(sbuf[64 + d], wb, b1v);
        }
        const float bb = b1[h];
        g_xa[(row0    ) * H + h] = a0 + bb;
        g_xa[(row0 + 1) * H + h] = a1 + bb;
        g_xb[(row0    ) * H + h] = b0;
        g_xb[(row0 + 1) * H + h] = b1v;
    }
}

// ---------------------------------------------------------------------------
// Persistent pair kernel: 296 CTAs, ticket queue over 4096 tiles.
// W2 staged ONCE per CTA; per tile: stage xa/xb, build A=fp16(relu(xa+xb)),
// 8x m16n8k16 k-steps, epilogue relu(+b2)+pair-sum -> slotted atomicAdd.
// ---------------------------------------------------------------------------
__global__ __launch_bounds__(256, 2) void pair_mma_kernel(const float* __restrict__ b2)
{
    extern __shared__ __align__(16) char smem[];
    const uint32_t S0 = smem_u32(smem);
    __shared__ int s_tile;

    const int t = threadIdx.x;
    const int lane = t & 31, w = t >> 5;
    const int wm = w >> 2, wn = w & 3;          // 2 x 4 warp grid

    // ---- stage W2^T (fp16) into padded smem rows -- once per CTA ----
    {
        uint32_t* dstW = (uint32_t*)(smem + OFF_B);
        const uint32_t* srcW = g_W2t;
#pragma unroll
        for (int it = 0; it < 32; ++it) {
            const int e = t + 256 * it;         // [0, 8192)
            dstW[(e >> 6) * 68 + (e & 63)] = srcW[e];
        }
        if (t < 128) ((float*)(smem + OFF_B2))[t] = b2[t];
    }

    const uint32_t aBase = S0 + OFF_A
        + (uint32_t)(wm * 64 + (lane & 15)) * RSTRIDE + (uint32_t)((lane >> 4) << 4);
    const uint32_t bBase = S0 + OFF_B
        + (uint32_t)(wn * 32 + ((lane & 7) | ((lane >> 4) << 3))) * RSTRIDE
        + (uint32_t)(((lane >> 3) & 1) << 4);

    while (true) {
        if (t == 0) s_tile = atomicAdd(&g_ticket, 1);
        __syncthreads();
        const int tile = s_tile;
        if (tile >= NTILES) break;

        const int b  = tile >> 11;
        const int r  = tile & 2047;
        const int i0 = (r >> 6) * 16;
        const int jx = r & 63;
        const int j0 = jx * 8;

        // ---- stage xa/xb rows (fp32) ----
        {
            const float4* xaG = (const float4*)(g_xa + (size_t)(b * N_TOK + j0) * H);
            const float4* xbG = (const float4*)(g_xb + (size_t)(b * N_TOK + i0) * H);
            float4* sxa = (float4*)(smem + OFF_XA);
            float4* sxb = (float4*)(smem + OFF_XB);
            sxa[t] = xaG[t];                                // 8*32 = 256 float4
            sxb[t] = xbG[t];
            sxb[t + 256] = xbG[t + 256];                    // 16*32 = 512 float4
        }
        __syncthreads();

        // ---- build A tile: row p = il*8+jl, A[p][k] = fp16(relu(xa+xb)) ----
        {
            const float* sxa = (const float*)(smem + OFF_XA);
            const float* sxb = (const float*)(smem + OFF_XB);
            uint32_t* sA = (uint32_t*)(smem + OFF_A);
#pragma unroll
            for (int it = 0; it < 32; ++it) {
                const int e = t + 256 * it;     // [0, 8192) half2 words
                const int row = e >> 6, q = e & 63;
                const int jl = row & 7, il = row >> 3;
                const float2 va = *(const float2*)&sxa[jl * H + 2 * q];
                const float2 vb = *(const float2*)&sxb[il * H + 2 * q];
                const __half2 h2 = __floats2half2_rn(fmaxf(va.x + vb.x, 0.f),
                                                     fmaxf(va.y + vb.y, 0.f));
                sA[row * 68 + q] = *(const uint32_t*)&h2;
            }
        }
        __syncthreads();

        // ---- main loop: 8 k-steps of m16n8k16 ----
        float acc[4][4][4];
#pragma unroll
        for (int a = 0; a < 4; ++a)
#pragma unroll
            for (int c = 0; c < 4; ++c)
#pragma unroll
                for (int rr = 0; rr < 4; ++rr) acc[a][c][rr] = 0.f;

#pragma unroll
        for (int ks = 0; ks < 8; ++ks) {
            const uint32_t kb = (uint32_t)ks * 32u;
            uint32_t a_frag[4][4], b_frag[2][4];
#pragma unroll
            for (int mb = 0; mb < 4; ++mb)
                ldmatrix_x4(a_frag[mb], aBase + (uint32_t)mb * (16u * RSTRIDE) + kb);
#pragma unroll
            for (int nb = 0; nb < 2; ++nb)
                ldmatrix_x4(b_frag[nb], bBase + (uint32_t)nb * (16u * RSTRIDE) + kb);
#pragma unroll
            for (int mb = 0; mb < 4; ++mb)
#pragma unroll
                for (int nb = 0; nb < 2; ++nb) {
                    mma_f16(acc[mb][nb * 2 + 0], a_frag[mb], b_frag[nb][0], b_frag[nb][1]);
                    mma_f16(acc[mb][nb * 2 + 1], a_frag[mb], b_frag[nb][2], b_frag[nb][3]);
                }
        }

        // ---- epilogue: relu(+b2), sum over 128 pairs ----
        const float* sb2 = (const float*)(smem + OFF_B2);
        float* red = (float*)(smem + OFF_RED);
#pragma unroll
        for (int n8 = 0; n8 < 4; ++n8) {
            const int colA = wn * 32 + n8 * 8 + (lane & 3) * 2;
            const float b2a = sb2[colA], b2b = sb2[colA + 1];
            float pa = 0.f, pb = 0.f;
#pragma unroll
            for (int mb = 0; mb < 4; ++mb) {
                const float* c = acc[mb][n8];
                pa += fmaxf(c[0] + b2a, 0.f) + fmaxf(c[2] + b2a, 0.f);
                pb += fmaxf(c[1] + b2b, 0.f) + fmaxf(c[3] + b2b, 0.f);
            }
#pragma unroll
            for (int s = 16; s >= 4; s >>= 1) {
                pa += __shfl_xor_sync(0xFFFFFFFFu, pa, s);
                pb += __shfl_xor_sync(0xFFFFFFFFu, pb, s);
            }
            if (lane < 4) {
                red[w * 32 + n8 * 8 + lane * 2]     = pa;
                red[w * 32 + n8 * 8 + lane * 2 + 1] = pb;
            }
        }
        __syncthreads();
        if (t < 128) {
            const int cl = t & 31, wnb = t >> 5;
            const float s = red[wnb * 32 + cl] + red[(4 + wnb) * 32 + cl];
            atomicAdd(&g_pooled_part[(b * 32 + (jx & 31)) * H + t], s);
        }
    }
}

// ---------------------------------------------------------------------------
// tail: o = relu(pooled @ M + d) with M summed from 4 partials inline;
// out = o @ V2 + c2. grid=2, 1024 threads, k-split 8.
// ---------------------------------------------------------------------------
__global__ __launch_bounds__(1024) void tail_kernel(const float* __restrict__ V2,
                                                    const float* __restrict__ c2,
                                                    float* __restrict__ out)
{
    __shared__ float sp[H];          // pooled
    __shared__ float so[H];          // o
    __shared__ float part[8][H];
    const int b = blockIdx.x;
    const int t = threadIdx.x;

    // stage pooled: sum the 32 contention slots
    if (t < H) {
        float s = 0.f;
#pragma unroll 8
        for (int sl = 0; sl < 32; ++sl) s += g_pooled_part[(b * 32 + sl) * H + t];
        sp[t] = s;
    }
    __syncthreads();

    // layer 1: o = relu(pooled @ (sum_s Mpart_s) + d)   (8 k-slices x 128 out)
    {
        const int ks = t >> 7, h = t & 127;
        const int k0 = ks * 16;
        float s0 = 0.f, s1 = 0.f, s2 = 0.f, s3 = 0.f;
#pragma unroll
        for (int sl = 0; sl < 4; ++sl) {
            const float* Mp = g_Mpart + sl * (H * H);
#pragma unroll
            for (int k = 0; k < 16; k += 4) {
                s0 = fmaf(sp[k0 + k],     Mp[(k0 + k) * H + h],     s0);
                s1 = fmaf(sp[k0 + k + 1], Mp[(k0 + k + 1) * H + h], s1);
                s2 = fmaf(sp[k0 + k + 2], Mp[(k0 + k + 2) * H + h], s2);
                s3 = fmaf(sp[k0 + k + 3], Mp[(k0 + k + 3) * H + h], s3);
            }
        }
        part[ks][h] = (s0 + s1) + (s2 + s3);
    }
    __syncthreads();
    if (t < H) {
        float v = g_d[t];
#pragma unroll
        for (int ks = 0; ks < 8; ++ks) v += part[ks][t];
        so[t] = v > 0.f ? v : 0.f;
    }
    __syncthreads();

    // layer 2: out = o @ V2 + c2            (8 k-slices x 64 outputs)
    if (t < 512) {
        const int ks = t >> 6, o = t & 63;
        const int k0 = ks * 16;
        float s0 = 0.f, s1 = 0.f, s2 = 0.f, s3 = 0.f;
#pragma unroll
        for (int k = 0; k < 16; k += 4) {
            s0 = fmaf(so[k0 + k],     V2[(k0 + k) * OUTD + o],     s0);
            s1 = fmaf(so[k0 + k + 1], V2[(k0 + k + 1) * OUTD + o], s1);
            s2 = fmaf(so[k0 + k + 2], V2[(k0 + k + 2) * OUTD + o], s2);
            s3 = fmaf(so[k0 + k + 3], V2[(k0 + k + 3) * OUTD + o], s3);
        }
        part[ks][o] = (s0 + s1) + (s2 + s3);
    }
    __syncthreads();
    if (t < OUTD) {
        float v = c2[t];
#pragma unroll
        for (int ks = 0; ks < 8; ++ks) v += part[ks][t];
        out[b * OUTD + t] = v;
    }
}

// ---------------------------------------------------------------------------
extern "C" void kernel_launch(void* const* d_in, const int* in_sizes, int n_in,
                              void* d_out, int out_size)
{
    const float* x  = (const float*)d_in[0];
    const float* W1 = (const float*)d_in[1];
    const float* b1 = (const float*)d_in[2];
    const float* W2 = (const float*)d_in[3];
    const float* b2 = (const float*)d_in[4];
    const float* W3 = (const float*)d_in[5];
    const float* b3 = (const float*)d_in[6];
    const float* V1 = (const float*)d_in[7];
    const float* c1 = (const float*)d_in[8];
    const float* V2 = (const float*)d_in[9];
    const float* c2 = (const float*)d_in[10];
    float* out = (float*)d_out;

    setup_kernel<<<1161, 128>>>(x, W1, b1, W2, W3, b3, V1, c1, V2);

    cudaFuncSetAttribute(pair_mma_kernel, cudaFuncAttributeMaxDynamicSharedMemorySize,
                         (int)SMEM_BYTES);
    pair_mma_kernel<<<PAIR_GRID, 256, SMEM_BYTES>>>(b2);

    tail_kernel<<<B_SZ, 1024>>>(V2, c2, out);
}